// round 7
// baseline (speedup 1.0000x reference)
#include <cuda_runtime.h>
#include <math.h>

// Problem shape (fixed by the reference's setup_inputs)
#define Bn 4
#define Tn 8192
#define Dn 1024
#define D4n (Dn / 4)       // 256 float4 groups across channels
#define Ln 32              // chunk length along time
#define Cn (Tn / Ln)       // 256 chunks
#define NIT (Cn * Bn * D4n)    // 262144 work items
#define NTH (NIT / 2)          // 131072 threads; 2 rounds each
#define STRIDE (Bn * D4n)      // item-index stride between adjacent chunks

// Per-channel tables (double closed form, computed once per launch)
__device__ float2 g_r [Dn];    // r   = exp(-|a|) (cos f, sin f)
__device__ float2 g_rL[Dn];    // r^L
// Decoupled-lookback state. agg/pref: 2 float4 per item (4 complex channels).
__device__ float4 g_agg [NIT * 2];
__device__ float4 g_pref[NIT * 2];
__device__ int    g_flag[NIT]; // 0 = none, 1 = aggregate ready, 2 = prefix ready

// ---------------------------------------------------------------------------
__global__ void k_setup(const float* __restrict__ decay,
                        const float* __restrict__ freq)
{
    int tid = blockIdx.x * blockDim.x + threadIdx.x;
    if (tid >= 2 * Dn) return;
    int d = tid % Dn;
    double span = (tid < Dn) ? 1.0 : (double)Ln;
    double a = fabs((double)decay[d]);
    double f = (double)freq[d];
    double g = exp(-a * span);
    float2 v = make_float2((float)(g * cos(f * span)),
                           (float)(g * sin(f * span)));
    if (tid < Dn) g_r[d] = v; else g_rL[d] = v;
}

// Reset flags every launch (graph replays reuse device globals).
__global__ void k_clear()
{
    int i = blockIdx.x * blockDim.x + threadIdx.x;
    if (i < NIT) g_flag[i] = 0;
}

// ---------------------------------------------------------------------------
// Fused single-pass chunked scan with decoupled lookback.
// ---------------------------------------------------------------------------
__global__ __launch_bounds__(256, 4)
void k_fused(const float4* __restrict__ x, float4* __restrict__ y)
{
    const int t = blockIdx.x * blockDim.x + threadIdx.x;
    volatile int* vflag = g_flag;

#pragma unroll 1
    for (int round = 0; round < 2; round++) {
        const int item = round * NTH + t;
        const int d4 = item % D4n;
        const int b  = (item / D4n) % Bn;
        const int c  = item / (D4n * Bn);

        const float4* rp  = (const float4*)g_r;
        const float4* rLp = (const float4*)g_rL;
        float4 r01 = rp [2 * d4], r23 = rp [2 * d4 + 1];
        float4 l01 = rLp[2 * d4], l23 = rLp[2 * d4 + 1];
        float rre[4] = {r01.x, r01.z, r23.x, r23.z};
        float rim[4] = {r01.y, r01.w, r23.y, r23.w};
        float lre[4] = {l01.x, l01.z, l23.x, l23.z};
        float lim[4] = {l01.y, l01.w, l23.y, l23.w};

        const float4* xp = x + (size_t)(b * Tn + c * Ln) * D4n + d4;

        // ---- local recurrence (zero init) -> aggregate A ----
        float Are[4] = {0.f, 0.f, 0.f, 0.f};
        float Aim[4] = {0.f, 0.f, 0.f, 0.f};
#pragma unroll 8
        for (int j = 0; j < Ln; j++) {
            float4 xv = xp[(size_t)j * D4n];
            float xr[4] = {xv.x, xv.y, xv.z, xv.w};
#pragma unroll
            for (int k = 0; k < 4; k++) {
                float nre = fmaf(rre[k], Are[k], fmaf(-rim[k], Aim[k], xr[k]));
                float nim = fmaf(rre[k], Aim[k], rim[k] * Are[k]);
                Are[k] = nre;
                Aim[k] = nim;
            }
        }

        // ---- publish / lookback -> carry (state at chunk start) ----
        float cre[4] = {0.f, 0.f, 0.f, 0.f};
        float cim[4] = {0.f, 0.f, 0.f, 0.f};

        if (c == 0) {
            // prefix = aggregate, publish directly
            g_pref[2 * item + 0] = make_float4(Are[0], Aim[0], Are[1], Aim[1]);
            g_pref[2 * item + 1] = make_float4(Are[2], Aim[2], Are[3], Aim[3]);
            __threadfence();
            vflag[item] = 2;
        } else {
            // publish aggregate so successors can progress
            g_agg[2 * item + 0] = make_float4(Are[0], Aim[0], Are[1], Aim[1]);
            g_agg[2 * item + 1] = make_float4(Are[2], Aim[2], Are[3], Aim[3]);
            __threadfence();
            vflag[item] = 1;

            // lookback: acc + w * (...) walking predecessors
            float accre[4] = {0.f, 0.f, 0.f, 0.f};
            float accim[4] = {0.f, 0.f, 0.f, 0.f};
            float wre[4] = {1.f, 1.f, 1.f, 1.f};
            float wim[4] = {0.f, 0.f, 0.f, 0.f};
            int look = item - STRIDE;
            while (true) {
                int f;
                do { f = vflag[look]; } while (f == 0);
                __threadfence();   // acquire: order value loads after flag
                if (f == 2) {
                    float4 p0 = __ldcg(&g_pref[2 * look + 0]);
                    float4 p1 = __ldcg(&g_pref[2 * look + 1]);
                    float pre[4] = {p0.x, p0.z, p1.x, p1.z};
                    float pim[4] = {p0.y, p0.w, p1.y, p1.w};
#pragma unroll
                    for (int k = 0; k < 4; k++) {
                        cre[k] = fmaf(wre[k], pre[k], fmaf(-wim[k], pim[k], accre[k]));
                        cim[k] = fmaf(wre[k], pim[k], fmaf(wim[k], pre[k], accim[k]));
                    }
                    break;
                } else {
                    float4 a0 = __ldcg(&g_agg[2 * look + 0]);
                    float4 a1 = __ldcg(&g_agg[2 * look + 1]);
                    float are[4] = {a0.x, a0.z, a1.x, a1.z};
                    float aim[4] = {a0.y, a0.w, a1.y, a1.w};
#pragma unroll
                    for (int k = 0; k < 4; k++) {
                        accre[k] = fmaf(wre[k], are[k], fmaf(-wim[k], aim[k], accre[k]));
                        accim[k] = fmaf(wre[k], aim[k], fmaf(wim[k], are[k], accim[k]));
                        float nwre = fmaf(wre[k], lre[k], -wim[k] * lim[k]);
                        float nwim = fmaf(wre[k], lim[k],  wim[k] * lre[k]);
                        wre[k] = nwre;
                        wim[k] = nwim;
                    }
                    look -= STRIDE;
                }
            }

            // publish inclusive prefix: P = r^L * carry + A
            float pre[4], pim[4];
#pragma unroll
            for (int k = 0; k < 4; k++) {
                pre[k] = fmaf(lre[k], cre[k], fmaf(-lim[k], cim[k], Are[k]));
                pim[k] = fmaf(lre[k], cim[k], fmaf( lim[k], cre[k], Aim[k]));
            }
            g_pref[2 * item + 0] = make_float4(pre[0], pim[0], pre[1], pim[1]);
            g_pref[2 * item + 1] = make_float4(pre[2], pim[2], pre[3], pim[3]);
            __threadfence();
            vflag[item] = 2;
        }

        // ---- replay seeded with carry; x re-read is L2-hot; write y ----
        float zre[4] = {cre[0], cre[1], cre[2], cre[3]};
        float zim[4] = {cim[0], cim[1], cim[2], cim[3]};
        float4* yp = y + (size_t)(b * Tn + c * Ln) * D4n + d4;
#pragma unroll 8
        for (int j = 0; j < Ln; j++) {
            float4 xv = xp[(size_t)j * D4n];
            float xr[4] = {xv.x, xv.y, xv.z, xv.w};
#pragma unroll
            for (int k = 0; k < 4; k++) {
                float nre = fmaf(rre[k], zre[k], fmaf(-rim[k], zim[k], xr[k]));
                float nim = fmaf(rre[k], zim[k], rim[k] * zre[k]);
                zre[k] = nre;
                zim[k] = nim;
            }
            __stcs(&yp[(size_t)j * D4n],
                   make_float4(zre[0], zre[1], zre[2], zre[3]));
        }
    }
}

// ---------------------------------------------------------------------------
extern "C" void kernel_launch(void* const* d_in, const int* in_sizes, int n_in,
                              void* d_out, int out_size)
{
    const float* x     = (const float*)d_in[0];
    const float* decay = (const float*)d_in[1];
    const float* freq  = (const float*)d_in[2];
    float* y = (float*)d_out;

    k_setup<<<(2 * Dn + 255) / 256, 256>>>(decay, freq);
    k_clear<<<(NIT + 255) / 256, 256>>>();
    k_fused<<<NTH / 256, 256>>>((const float4*)x, (float4*)y);
}

// round 8
// speedup vs baseline: 1.1754x; 1.1754x over previous
#include <cuda_runtime.h>
#include <math.h>

// Problem shape (fixed by the reference's setup_inputs)
#define Bn 4
#define Tn 8192
#define Dn 1024
#define D4n (Dn / 4)       // 256 float4 groups across channels
#define Ln 32              // chunk length along time
#define Cn (Tn / Ln)       // 256 chunks
#define CPL 8              // chunks per lane in the warp scan
#define NIT (Cn * Bn * D4n)    // 262144 work items
#define NTH (NIT / 2)          // 131072 threads; 2 chunk-rounds each
#define GRID_CTAS (NTH / 256)  // 512 CTAs -> all co-resident (4/SM cap)

// Per-channel tables (double closed form, computed in k_setup):
__device__ float2 g_r [Dn];      // r = exp(-|a|)(cos f, sin f)
__device__ float2 g_rL[Dn];      // r^L
__device__ float2 g_w [5][Dn];   // r^(8L * 2^s)

// Scratch (L2-resident): chunk-end and carry-in states, [c][b][k][d4].
__device__ float2 g_ends [NIT * 4 / 4 * 4];   // = Cn*Bn*4*D4n float2
__device__ float2 g_carry[Cn * Bn * 4 * D4n];

// Software grid barrier (2 slots, reset each launch by k_setup).
__device__ int g_bar[2];

// ---------------------------------------------------------------------------
// setup: one (exp,cos,sin) double triple per thread; 7*Dn = 7168 threads.
// job j: 0 -> g_r, 1 -> g_rL, 2..6 -> g_w[j-2]. Thread 0 resets barriers.
// ---------------------------------------------------------------------------
__global__ void k_setup(const float* __restrict__ decay,
                        const float* __restrict__ freq)
{
    int tid = blockIdx.x * blockDim.x + threadIdx.x;
    if (tid == 0) { g_bar[0] = 0; g_bar[1] = 0; }
    if (tid >= 7 * Dn) return;
    int d = tid % Dn;
    int j = tid / Dn;

    double span;
    if (j == 0)      span = 1.0;
    else if (j == 1) span = (double)Ln;
    else             span = (double)(CPL * Ln * (1 << (j - 2)));

    double a = fabs((double)decay[d]);
    double f = (double)freq[d];
    double g = exp(-a * span);
    float2 v = make_float2((float)(g * cos(f * span)),
                           (float)(g * sin(f * span)));

    if (j == 0)      g_r[d]      = v;
    else if (j == 1) g_rL[d]     = v;
    else             g_w[j-2][d] = v;
}

// ---------------------------------------------------------------------------
__device__ __forceinline__ void gsync(int slot)
{
    __syncthreads();
    if (threadIdx.x == 0) {
        __threadfence();                       // release prior writes
        atomicAdd(&g_bar[slot], 1);
        volatile int* b = &g_bar[slot];
        while (*b < GRID_CTAS) { }
        __threadfence();                       // acquire
    }
    __syncthreads();
}

// ---------------------------------------------------------------------------
// Fused: phase1 (local recurrences) | gsync | phase2 (warp scan) | gsync |
// phase3 (replay, reverse round order so x re-reads hit L2).
// ---------------------------------------------------------------------------
__global__ __launch_bounds__(256, 4)
void k_fused(const float4* __restrict__ x, float4* __restrict__ y)
{
    const int t = blockIdx.x * blockDim.x + threadIdx.x;

    // ---------------- phase 1: local recurrence per chunk ----------------
    {
        const int d4 = t % D4n;
        const float4* rp = (const float4*)g_r;
        float4 r01 = rp[2 * d4], r23 = rp[2 * d4 + 1];
        float rre[4] = {r01.x, r01.z, r23.x, r23.z};
        float rim[4] = {r01.y, r01.w, r23.y, r23.w};

#pragma unroll 1
        for (int round = 0; round < 2; round++) {
            const int item = round * NTH + t;
            const int b = (item / D4n) % Bn;
            const int c = item / (D4n * Bn);

            float zre[4] = {0.f, 0.f, 0.f, 0.f};
            float zim[4] = {0.f, 0.f, 0.f, 0.f};
            const float4* xp = x + (size_t)(b * Tn + c * Ln) * D4n + d4;
#pragma unroll 8
            for (int j = 0; j < Ln; j++) {
                float4 xv = xp[(size_t)j * D4n];
                float xr[4] = {xv.x, xv.y, xv.z, xv.w};
#pragma unroll
                for (int k = 0; k < 4; k++) {
                    float nre = fmaf(rre[k], zre[k], fmaf(-rim[k], zim[k], xr[k]));
                    float nim = fmaf(rre[k], zim[k], rim[k] * zre[k]);
                    zre[k] = nre;
                    zim[k] = nim;
                }
            }
#pragma unroll
            for (int k = 0; k < 4; k++)
                g_ends[((c * Bn + b) * 4 + k) * D4n + d4] =
                    make_float2(zre[k], zim[k]);
        }
    }

    gsync(0);

    // ---------------- phase 2: warp-parallel scan over chunks ----------------
    {
        const int wid  = t >> 5;         // 0 .. Bn*Dn-1  (4096 series)
        const int lane = t & 31;
        const int d = wid % Dn;
        const int b = wid / Dn;
        const int d4 = d >> 2;
        const int k  = d & 3;

        float2 rL = g_rL[d];
        float rLre = rL.x, rLim = rL.y;

        float2 e[CPL];
        float Are = 0.0f, Aim = 0.0f;
#pragma unroll
        for (int i = 0; i < CPL; i++) {
            int c = lane * CPL + i;
            e[i] = *(const float2*)__builtin_assume_aligned(
                       &g_ends[((c * Bn + b) * 4 + k) * D4n + d4], 8);
            float nre = fmaf(rLre, Are, fmaf(-rLim, Aim, e[i].x));
            float nim = fmaf(rLre, Aim, fmaf(rLim, Are, e[i].y));
            Are = nre; Aim = nim;
        }

        float Sre = Are, Sim = Aim;
#pragma unroll
        for (int step = 0; step < 5; step++) {
            int off = 1 << step;
            float2 w = g_w[step][d];
            float Pre = __shfl_up_sync(0xFFFFFFFFu, Sre, off);
            float Pim = __shfl_up_sync(0xFFFFFFFFu, Sim, off);
            if (lane >= off) {
                Sre = fmaf(w.x, Pre, fmaf(-w.y, Pim, Sre));
                Sim = fmaf(w.x, Pim, fmaf(w.y, Pre, Sim));
            }
        }

        float Cre = __shfl_up_sync(0xFFFFFFFFu, Sre, 1);
        float Cim = __shfl_up_sync(0xFFFFFFFFu, Sim, 1);
        if (lane == 0) { Cre = 0.0f; Cim = 0.0f; }

#pragma unroll
        for (int i = 0; i < CPL; i++) {
            int c = lane * CPL + i;
            g_carry[((c * Bn + b) * 4 + k) * D4n + d4] = make_float2(Cre, Cim);
            float nre = fmaf(rLre, Cre, fmaf(-rLim, Cim, e[i].x));
            float nim = fmaf(rLre, Cim, fmaf(rLim, Cre, e[i].y));
            Cre = nre; Cim = nim;
        }
    }

    gsync(1);

    // ---------------- phase 3: replay with carry; reverse round order ----------------
    {
        const int d4 = t % D4n;
        const float4* rp = (const float4*)g_r;
        float4 r01 = rp[2 * d4], r23 = rp[2 * d4 + 1];
        float rre[4] = {r01.x, r01.z, r23.x, r23.z};
        float rim[4] = {r01.y, r01.w, r23.y, r23.w};

#pragma unroll 1
        for (int round = 1; round >= 0; round--) {   // round 1 first: x L2-hot
            const int item = round * NTH + t;
            const int b = (item / D4n) % Bn;
            const int c = item / (D4n * Bn);

            float zre[4], zim[4];
#pragma unroll
            for (int k = 0; k < 4; k++) {
                float2 cc = *(const float2*)&g_carry[((c * Bn + b) * 4 + k) * D4n + d4];
                zre[k] = cc.x;
                zim[k] = cc.y;
            }

            const float4* xp = x + (size_t)(b * Tn + c * Ln) * D4n + d4;
            float4*       yp = y + (size_t)(b * Tn + c * Ln) * D4n + d4;
#pragma unroll 8
            for (int j = 0; j < Ln; j++) {
                float4 xv = xp[(size_t)j * D4n];
                float xr[4] = {xv.x, xv.y, xv.z, xv.w};
#pragma unroll
                for (int k = 0; k < 4; k++) {
                    float nre = fmaf(rre[k], zre[k], fmaf(-rim[k], zim[k], xr[k]));
                    float nim = fmaf(rre[k], zim[k], rim[k] * zre[k]);
                    zre[k] = nre;
                    zim[k] = nim;
                }
                __stcs(&yp[(size_t)j * D4n],
                       make_float4(zre[0], zre[1], zre[2], zre[3]));
            }
        }
    }
}

// ---------------------------------------------------------------------------
extern "C" void kernel_launch(void* const* d_in, const int* in_sizes, int n_in,
                              void* d_out, int out_size)
{
    const float* x     = (const float*)d_in[0];
    const float* decay = (const float*)d_in[1];
    const float* freq  = (const float*)d_in[2];
    float* y = (float*)d_out;

    k_setup<<<(7 * Dn + 255) / 256, 256>>>(decay, freq);
    k_fused<<<GRID_CTAS, 256>>>((const float4*)x, (float4*)y);
}